// round 8
// baseline (speedup 1.0000x reference)
#include <cuda_runtime.h>
#include <math.h>

#define NN 100000
#define D1 128
#define D2 64
#define EMAX 4000000
#define SCAN_BLK 1024
#define MAXNB 128

typedef unsigned long long ull;

// ---------------- scratch (static __device__ — no runtime allocation) ----------------
__device__ float  g_dis[NN];                        // rsqrt(deg+1)
__device__ float2 g_dis2[NN];                       // duplicated {d,d} for packed math
__device__ int    g_deg[NN];
__device__ int    g_rowstart[NN];
__device__ int    g_cursor[NN];
__device__ int    g_csr[EMAX];
__device__ int    g_blocksum[MAXNB];
__device__ int    g_blockoff[MAXNB];
__device__ float  g_H1[(size_t)NN * D1];
__device__ float  g_A1[(size_t)NN * D1];
__device__ float  g_H2[(size_t)NN * D2];
__device__ float  g_A2[(size_t)NN * D2];
__device__ int    g_is64;

// ---------------- f32x2 helpers ----------------
__device__ __forceinline__ ull pack2(float lo, float hi) {
    ull r; asm("mov.b64 %0, {%1,%2};" : "=l"(r) : "f"(lo), "f"(hi)); return r;
}
__device__ __forceinline__ float2 unpack2(ull u) {
    float2 f; asm("mov.b64 {%0,%1}, %2;" : "=f"(f.x), "=f"(f.y) : "l"(u)); return f;
}
__device__ __forceinline__ void ffma2(ull& d, ull a, ull b, ull c) {
    asm("fma.rn.f32x2 %0, %1, %2, %3;" : "=l"(d) : "l"(a), "l"(b), "l"(c));
}
__device__ __forceinline__ void fmul2(ull& d, ull a, ull b) {
    asm("mul.rn.f32x2 %0, %1, %2;" : "=l"(d) : "l"(a), "l"(b));
}

__device__ __forceinline__ int load_idx(const void* ei, long long pos, int is64) {
    return is64 ? (int)((const long long*)ei)[pos] : ((const int*)ei)[pos];
}

// ---------------- setup: dtype detect + zero degree ----------------
__global__ void setup_kernel(const unsigned int* ei, int n) {
    int i = blockIdx.x * blockDim.x + threadIdx.x;
    if (i < n) g_deg[i] = 0;
    if (blockIdx.x == 0) {
        __shared__ int any;
        if (threadIdx.x == 0) any = 0;
        __syncthreads();
        int local = 0;
        for (int j = threadIdx.x; j < 2048; j += blockDim.x)
            if (ei[2 * j + 1] != 0u) local = 1;
        if (local) any = 1;
        __syncthreads();
        if (threadIdx.x == 0) g_is64 = (any == 0) ? 1 : 0;
    }
}

__global__ void count_kernel(const void* __restrict__ ei, long long E) {
    long long e = (long long)blockIdx.x * blockDim.x + threadIdx.x;
    if (e >= E) return;
    int dst = load_idx(ei, E + e, g_is64);
    atomicAdd(&g_deg[dst], 1);
}

// ---- 2-level exclusive scan over g_deg -> rowstart/cursor; also dis ----
__global__ void scanA_kernel(int n) {
    __shared__ int s[SCAN_BLK];
    int i = blockIdx.x * SCAN_BLK + threadIdx.x;
    s[threadIdx.x] = (i < n) ? g_deg[i] : 0;
    __syncthreads();
    for (int off = SCAN_BLK / 2; off > 0; off >>= 1) {
        if (threadIdx.x < off) s[threadIdx.x] += s[threadIdx.x + off];
        __syncthreads();
    }
    if (threadIdx.x == 0) g_blocksum[blockIdx.x] = s[0];
}

__global__ void scanB_kernel(int nb) {
    __shared__ int s[MAXNB];
    int v = (threadIdx.x < nb) ? g_blocksum[threadIdx.x] : 0;
    s[threadIdx.x] = v;
    __syncthreads();
    for (int off = 1; off < MAXNB; off <<= 1) {
        int t = (threadIdx.x >= off) ? s[threadIdx.x - off] : 0;
        __syncthreads();
        s[threadIdx.x] += t;
        __syncthreads();
    }
    if (threadIdx.x < nb) g_blockoff[threadIdx.x] = s[threadIdx.x] - v;
}

__global__ void scanC_kernel(int n) {
    __shared__ int s[SCAN_BLK];
    int i = blockIdx.x * SCAN_BLK + threadIdx.x;
    int v = (i < n) ? g_deg[i] : 0;
    s[threadIdx.x] = v;
    __syncthreads();
    for (int off = 1; off < SCAN_BLK; off <<= 1) {
        int t = (threadIdx.x >= off) ? s[threadIdx.x - off] : 0;
        __syncthreads();
        s[threadIdx.x] += t;
        __syncthreads();
    }
    if (i < n) {
        int excl = s[threadIdx.x] - v + g_blockoff[blockIdx.x];
        g_rowstart[i] = excl;
        g_cursor[i] = excl;
        float d = rsqrtf((float)(v + 1));
        g_dis[i] = d;
        g_dis2[i] = make_float2(d, d);
    }
}

__global__ void fill_kernel(const void* __restrict__ ei, long long E) {
    long long e = (long long)blockIdx.x * blockDim.x + threadIdx.x;
    if (e >= E) return;
    const int is64 = g_is64;
    int src = load_idx(ei, e, is64);
    int dst = load_idx(ei, E + e, is64);
    int pos = atomicAdd(&g_cursor[dst], 1);
    g_csr[pos] = src;
}

// ---------------- register-tiled GEMM, packed staging, OUT-split ------------------
// H = X@W (optionally X <- relu(X+bin) on load). IN = 128.
// Block computes 128 rows x 64 cols. blockIdx.y selects the 64-col slab.
// 256 threads: tx = tid%8 (8 cols each), ty = tid/8 (4 rows each).
// x staged transposed AND duplicated ({v,v}) so FFMA2 needs zero MOVs.
template <int OUT, bool RELU_IN>
__global__ void __launch_bounds__(256, 3)
gemm_kernel(const float* __restrict__ X, const float* __restrict__ W,
            const float* __restrict__ bin, float* __restrict__ H, int n) {
    constexpr int IN = 128;
    constexpr int ROWS = 128;
    constexpr int KC = 16;
    constexpr int NCHUNK = IN / KC;                 // 8

    extern __shared__ float smem[];
    float*  Ws  = smem;                             // IN*64 floats = 32KB
    float2* xd0 = (float2*)(smem + IN * 64);        // KC*ROWS float2 = 16KB
    float2* xd1 = xd0 + KC * ROWS;                  // 16KB

    const int tid = threadIdx.x;
    const int tx = tid & 7;
    const int ty = tid >> 3;
    const int row0 = blockIdx.x * ROWS;
    const int cb = blockIdx.y;                      // col slab

    // load W slab [IN][64] (vectorized)
    {
        const float4* W4 = (const float4*)W;
        float4* Ws4 = (float4*)Ws;
        #pragma unroll
        for (int i = tid; i < IN * 64 / 4; i += 256) {
            const int k = i >> 4;                   // /16
            const int c4 = i & 15;
            Ws4[i] = W4[k * (OUT / 4) + cb * 16 + c4];
        }
    }

    // per-thread staging assignment: r = tid&127, covers 8 k-floats (2 float4)
    const int sr = tid & 127;
    const int shalf = tid >> 7;                     // 0/1
    float4 pf[2];

    auto LOADX = [&](int kc0) {
        const int row = row0 + sr;
        #pragma unroll
        for (int p = 0; p < 2; ++p) {
            const int ko = kc0 + shalf * 8 + p * 4;
            float4 v = make_float4(0.f, 0.f, 0.f, 0.f);
            if (row < n) {
                v = *(const float4*)&X[(size_t)row * IN + ko];
                if (RELU_IN) {
                    const float4 b = *(const float4*)&bin[ko];
                    v.x = fmaxf(v.x + b.x, 0.f);
                    v.y = fmaxf(v.y + b.y, 0.f);
                    v.z = fmaxf(v.z + b.z, 0.f);
                    v.w = fmaxf(v.w + b.w, 0.f);
                }
            }
            pf[p] = v;
        }
    };

    auto STOREX = [&](float2* buf) {
        #pragma unroll
        for (int p = 0; p < 2; ++p) {
            const int kl = shalf * 8 + p * 4;
            buf[(kl + 0) * ROWS + sr] = make_float2(pf[p].x, pf[p].x);
            buf[(kl + 1) * ROWS + sr] = make_float2(pf[p].y, pf[p].y);
            buf[(kl + 2) * ROWS + sr] = make_float2(pf[p].z, pf[p].z);
            buf[(kl + 3) * ROWS + sr] = make_float2(pf[p].w, pf[p].w);
        }
    };

    ull acc[4][4];
    #pragma unroll
    for (int j = 0; j < 4; ++j)
        #pragma unroll
        for (int p = 0; p < 4; ++p) acc[j][p] = 0ull;

    LOADX(0);
    STOREX(xd0);
    __syncthreads();

    for (int c = 0; c < NCHUNK; ++c) {
        float2* cur = (c & 1) ? xd1 : xd0;
        float2* nxt = (c & 1) ? xd0 : xd1;
        if (c + 1 < NCHUNK) LOADX((c + 1) * KC);

        const int kc0 = c * KC;
        #pragma unroll
        for (int kk = 0; kk < KC; ++kk) {
            // 4 duplicated x values = 2 x LDS.128
            const ulonglong2* xr = (const ulonglong2*)&cur[kk * ROWS + ty * 4];
            const ulonglong2 xA = xr[0];
            const ulonglong2 xB = xr[1];
            // 8 W cols = 4 ull = 2 x LDS.128
            const ulonglong2* wr = (const ulonglong2*)&Ws[(kc0 + kk) * 64 + tx * 8];
            const ulonglong2 wA = wr[0];
            const ulonglong2 wB = wr[1];

            ffma2(acc[0][0], xA.x, wA.x, acc[0][0]);
            ffma2(acc[0][1], xA.x, wA.y, acc[0][1]);
            ffma2(acc[0][2], xA.x, wB.x, acc[0][2]);
            ffma2(acc[0][3], xA.x, wB.y, acc[0][3]);
            ffma2(acc[1][0], xA.y, wA.x, acc[1][0]);
            ffma2(acc[1][1], xA.y, wA.y, acc[1][1]);
            ffma2(acc[1][2], xA.y, wB.x, acc[1][2]);
            ffma2(acc[1][3], xA.y, wB.y, acc[1][3]);
            ffma2(acc[2][0], xB.x, wA.x, acc[2][0]);
            ffma2(acc[2][1], xB.x, wA.y, acc[2][1]);
            ffma2(acc[2][2], xB.x, wB.x, acc[2][2]);
            ffma2(acc[2][3], xB.x, wB.y, acc[2][3]);
            ffma2(acc[3][0], xB.y, wA.x, acc[3][0]);
            ffma2(acc[3][1], xB.y, wA.y, acc[3][1]);
            ffma2(acc[3][2], xB.y, wB.x, acc[3][2]);
            ffma2(acc[3][3], xB.y, wB.y, acc[3][3]);
        }

        if (c + 1 < NCHUNK) STOREX(nxt);
        __syncthreads();
    }

    #pragma unroll
    for (int j = 0; j < 4; ++j) {
        const int row = row0 + ty * 4 + j;
        if (row >= n) continue;
        const float2 a0 = unpack2(acc[j][0]);
        const float2 a1 = unpack2(acc[j][1]);
        const float2 a2 = unpack2(acc[j][2]);
        const float2 a3 = unpack2(acc[j][3]);
        float* hp = &H[(size_t)row * OUT + cb * 64 + tx * 8];
        *(float4*)hp = make_float4(a0.x, a0.y, a1.x, a1.y);
        *(float4*)(hp + 4) = make_float4(a2.x, a2.y, a3.x, a3.y);
    }
}

// -------- gather: A[d] = dis[d] * ( dis[d]*H[d] + sum_{s in N(d)} dis[s]*H[s] ) ------
template <int D>
__global__ void gather_kernel(const float* __restrict__ H, float* __restrict__ A, int n) {
    constexpr int LPN = D / 4;
    const long long gt = (long long)blockIdx.x * blockDim.x + threadIdx.x;
    const int node = (int)(gt / LPN);
    const int l = (int)(gt % LPN);
    if (node >= n) return;

    const float4* __restrict__ h4 = (const float4*)H;
    const ull* __restrict__ dis2 = (const ull*)g_dis2;
    const size_t col = (size_t)node * LPN + l;
    const ull dd = __ldg(&dis2[node]);

    float4 sv = h4[col];
    ull acc0, acc1;
    fmul2(acc0, pack2(sv.x, sv.y), dd);
    fmul2(acc1, pack2(sv.z, sv.w), dd);

    const int beg = g_rowstart[node];
    const int cnt = g_deg[node];

    #pragma unroll 4
    for (int j = 0; j < cnt; ++j) {
        const int src = __ldg(&g_csr[beg + j]);
        const ull ss = __ldg(&dis2[src]);
        const float4 v = h4[(size_t)src * LPN + l];
        ffma2(acc0, pack2(v.x, v.y), ss, acc0);
        ffma2(acc1, pack2(v.z, v.w), ss, acc1);
    }

    fmul2(acc0, acc0, dd);
    fmul2(acc1, acc1, dd);
    const float2 a = unpack2(acc0);
    const float2 b = unpack2(acc1);
    ((float4*)A)[col] = make_float4(a.x, a.y, b.x, b.y);
}

// ---------------- final: out = softmax(relu(A2+b2) @ Wf + bf) ----------------
__global__ void final_kernel(const float* __restrict__ A2, const float* __restrict__ b2,
                             const float* __restrict__ Wf, const float* __restrict__ bf,
                             float* __restrict__ out, int n) {
    __shared__ float Wfs[64 * 10];
    __shared__ float bfs[10];
    __shared__ float b2s[64];
    for (int i = threadIdx.x; i < 640; i += blockDim.x) Wfs[i] = Wf[i];
    if (threadIdx.x < 10) bfs[threadIdx.x] = bf[threadIdx.x];
    if (threadIdx.x < 64) b2s[threadIdx.x] = b2[threadIdx.x];
    __syncthreads();

    const int i = blockIdx.x * blockDim.x + threadIdx.x;
    if (i >= n) return;

    float acc[10];
    #pragma unroll
    for (int c = 0; c < 10; ++c) acc[c] = bfs[c];

    #pragma unroll
    for (int kk = 0; kk < 64; kk += 4) {
        float4 v = *(const float4*)&A2[(size_t)i * 64 + kk];
        v.x = fmaxf(v.x + b2s[kk + 0], 0.f);
        v.y = fmaxf(v.y + b2s[kk + 1], 0.f);
        v.z = fmaxf(v.z + b2s[kk + 2], 0.f);
        v.w = fmaxf(v.w + b2s[kk + 3], 0.f);
        #pragma unroll
        for (int c = 0; c < 10; ++c) {
            acc[c] = fmaf(v.x, Wfs[(kk + 0) * 10 + c], acc[c]);
            acc[c] = fmaf(v.y, Wfs[(kk + 1) * 10 + c], acc[c]);
            acc[c] = fmaf(v.z, Wfs[(kk + 2) * 10 + c], acc[c]);
            acc[c] = fmaf(v.w, Wfs[(kk + 3) * 10 + c], acc[c]);
        }
    }

    float m = acc[0];
    #pragma unroll
    for (int c = 1; c < 10; ++c) m = fmaxf(m, acc[c]);
    float s = 0.f;
    float ex[10];
    #pragma unroll
    for (int c = 0; c < 10; ++c) { ex[c] = expf(acc[c] - m); s += ex[c]; }
    const float inv = 1.0f / s;
    #pragma unroll
    for (int c = 0; c < 10; ++c) out[(size_t)i * 10 + c] = ex[c] * inv;
}

// ---------------- launch ----------------
extern "C" void kernel_launch(void* const* d_in, const int* in_sizes, int n_in,
                              void* d_out, int out_size) {
    const float* x  = (const float*)d_in[0];
    const void*  ei = d_in[1];
    const float* W1 = (const float*)d_in[2];
    const float* b1 = (const float*)d_in[3];
    const float* W2 = (const float*)d_in[4];
    const float* b2 = (const float*)d_in[5];
    const float* Wf = (const float*)d_in[6];
    const float* bf = (const float*)d_in[7];
    float* out = (float*)d_out;

    const long long E = (long long)in_sizes[1] / 2;
    const int n = in_sizes[0] / D1;
    const int nb = (n + SCAN_BLK - 1) / SCAN_BLK;

    float *H1, *A1, *H2, *A2;
    cudaGetSymbolAddress((void**)&H1, g_H1);
    cudaGetSymbolAddress((void**)&A1, g_A1);
    cudaGetSymbolAddress((void**)&H2, g_H2);
    cudaGetSymbolAddress((void**)&A2, g_A2);

    // smem: W slab (32KB) + 2 packed x buffers (16KB each) = 64KB
    const int smem_g = 128 * 64 * 4 + 2 * 16 * 128 * 8;   // 65536
    cudaFuncSetAttribute(gemm_kernel<128, false>,
                         cudaFuncAttributeMaxDynamicSharedMemorySize, smem_g);
    cudaFuncSetAttribute(gemm_kernel<64, true>,
                         cudaFuncAttributeMaxDynamicSharedMemorySize, smem_g);

    const int rowb = (n + 127) / 128;

    // gemm1 stays at launch index 3 (ncu capture slot).
    setup_kernel<<<(n + 255) / 256, 256>>>((const unsigned int*)ei, n);
    if (E > 0) count_kernel<<<(int)((E + 255) / 256), 256>>>(ei, E);
    scanA_kernel<<<nb, SCAN_BLK>>>(n);
    gemm_kernel<128, false><<<dim3(rowb, 2), 256, smem_g>>>(x, W1, nullptr, H1, n);
    scanB_kernel<<<1, MAXNB>>>(nb);
    scanC_kernel<<<nb, SCAN_BLK>>>(n);
    if (E > 0) fill_kernel<<<(int)((E + 255) / 256), 256>>>(ei, E);

    gather_kernel<128><<<(int)(((long long)n * 32 + 255) / 256), 256>>>(H1, A1, n);

    gemm_kernel<64, true><<<dim3(rowb, 1), 256, smem_g>>>(A1, W2, b1, H2, n);
    gather_kernel<64><<<(int)(((long long)n * 16 + 255) / 256), 256>>>(H2, A2, n);

    final_kernel<<<(n + 255) / 256, 256>>>(A2, b2, Wf, bf, out, n);
}

// round 9
// speedup vs baseline: 1.3469x; 1.3469x over previous
#include <cuda_runtime.h>
#include <math.h>

#define NN 100000
#define D1 128
#define D2 64
#define EMAX 4000000
#define SCAN_BLK 1024
#define MAXNB 128

typedef unsigned long long ull;

// ---------------- scratch (static __device__ — no runtime allocation) ----------------
__device__ float  g_dis[NN];                        // rsqrt(deg+1)
__device__ float2 g_dis2[NN];                       // duplicated {d,d} for packed math
__device__ int    g_deg[NN];
__device__ int    g_rowstart[NN];
__device__ int    g_cursor[NN];
__device__ int    g_csr[EMAX];
__device__ int    g_blocksum[MAXNB];
__device__ int    g_blockoff[MAXNB];
__device__ float  g_H1[(size_t)NN * D1];
__device__ float  g_A1[(size_t)NN * D1];
__device__ float  g_H2[(size_t)NN * D2];
__device__ float  g_A2[(size_t)NN * D2];
__device__ int    g_is64;

// ---------------- f32x2 helpers ----------------
__device__ __forceinline__ ull pack2(float lo, float hi) {
    ull r; asm("mov.b64 %0, {%1,%2};" : "=l"(r) : "f"(lo), "f"(hi)); return r;
}
__device__ __forceinline__ float2 unpack2(ull u) {
    float2 f; asm("mov.b64 {%0,%1}, %2;" : "=f"(f.x), "=f"(f.y) : "l"(u)); return f;
}
__device__ __forceinline__ void ffma2(ull& d, ull a, ull b, ull c) {
    asm("fma.rn.f32x2 %0, %1, %2, %3;" : "=l"(d) : "l"(a), "l"(b), "l"(c));
}
__device__ __forceinline__ void fmul2(ull& d, ull a, ull b) {
    asm("mul.rn.f32x2 %0, %1, %2;" : "=l"(d) : "l"(a), "l"(b));
}

__device__ __forceinline__ int load_idx(const void* ei, long long pos, int is64) {
    return is64 ? (int)((const long long*)ei)[pos] : ((const int*)ei)[pos];
}

// ---------------- setup: dtype detect + zero degree ----------------
__global__ void setup_kernel(const unsigned int* ei, int n) {
    int i = blockIdx.x * blockDim.x + threadIdx.x;
    if (i < n) g_deg[i] = 0;
    if (blockIdx.x == 0) {
        __shared__ int any;
        if (threadIdx.x == 0) any = 0;
        __syncthreads();
        int local = 0;
        for (int j = threadIdx.x; j < 2048; j += blockDim.x)
            if (ei[2 * j + 1] != 0u) local = 1;
        if (local) any = 1;
        __syncthreads();
        if (threadIdx.x == 0) g_is64 = (any == 0) ? 1 : 0;
    }
}

__global__ void count_kernel(const void* __restrict__ ei, long long E) {
    long long e = (long long)blockIdx.x * blockDim.x + threadIdx.x;
    if (e >= E) return;
    int dst = load_idx(ei, E + e, g_is64);
    atomicAdd(&g_deg[dst], 1);
}

// ---- 2-level exclusive scan over g_deg -> rowstart/cursor; also dis ----
__global__ void scanA_kernel(int n) {
    __shared__ int s[SCAN_BLK];
    int i = blockIdx.x * SCAN_BLK + threadIdx.x;
    s[threadIdx.x] = (i < n) ? g_deg[i] : 0;
    __syncthreads();
    for (int off = SCAN_BLK / 2; off > 0; off >>= 1) {
        if (threadIdx.x < off) s[threadIdx.x] += s[threadIdx.x + off];
        __syncthreads();
    }
    if (threadIdx.x == 0) g_blocksum[blockIdx.x] = s[0];
}

__global__ void scanB_kernel(int nb) {
    __shared__ int s[MAXNB];
    int v = (threadIdx.x < nb) ? g_blocksum[threadIdx.x] : 0;
    s[threadIdx.x] = v;
    __syncthreads();
    for (int off = 1; off < MAXNB; off <<= 1) {
        int t = (threadIdx.x >= off) ? s[threadIdx.x - off] : 0;
        __syncthreads();
        s[threadIdx.x] += t;
        __syncthreads();
    }
    if (threadIdx.x < nb) g_blockoff[threadIdx.x] = s[threadIdx.x] - v;
}

__global__ void scanC_kernel(int n) {
    __shared__ int s[SCAN_BLK];
    int i = blockIdx.x * SCAN_BLK + threadIdx.x;
    int v = (i < n) ? g_deg[i] : 0;
    s[threadIdx.x] = v;
    __syncthreads();
    for (int off = 1; off < SCAN_BLK; off <<= 1) {
        int t = (threadIdx.x >= off) ? s[threadIdx.x - off] : 0;
        __syncthreads();
        s[threadIdx.x] += t;
        __syncthreads();
    }
    if (i < n) {
        int excl = s[threadIdx.x] - v + g_blockoff[blockIdx.x];
        g_rowstart[i] = excl;
        g_cursor[i] = excl;
        float d = rsqrtf((float)(v + 1));
        g_dis[i] = d;
        g_dis2[i] = make_float2(d, d);
    }
}

__global__ void fill_kernel(const void* __restrict__ ei, long long E) {
    long long e = (long long)blockIdx.x * blockDim.x + threadIdx.x;
    if (e >= E) return;
    const int is64 = g_is64;
    int src = load_idx(ei, e, is64);
    int dst = load_idx(ei, E + e, is64);
    int pos = atomicAdd(&g_cursor[dst], 1);
    g_csr[pos] = src;
}

// ---------------- register-tiled GEMM (8x8 per thread, f32x2 FMAs) ------------------
// Round-6 configuration (verified 102us). H = X@W, optional relu(X+bin) on load.
template <int OUT, bool RELU_IN>
__global__ void __launch_bounds__(256, 2)
gemm_kernel(const float* __restrict__ X, const float* __restrict__ W,
            const float* __restrict__ bin, float* __restrict__ H, int n) {
    constexpr int IN = 128;
    constexpr int TX = OUT / 8;
    constexpr int TY = 256 / TX;
    constexpr int ROWS = TY * 8;
    constexpr int KC = 16;
    constexpr int NCHUNK = IN / KC;
    constexpr int ELEMS = KC * ROWS;
    constexpr int PASSES = ELEMS / (256 * 4);

    extern __shared__ float smem[];
    float* Ws = smem;
    float* xT0 = smem + IN * OUT;
    float* xT1 = xT0 + ELEMS;

    const int tid = threadIdx.x;
    const int tx = tid % TX;
    const int ty = tid / TX;
    const int row0 = blockIdx.x * ROWS;

    for (int i = tid; i < IN * OUT; i += 256) Ws[i] = W[i];

    float4 pf[PASSES];

    auto LOADX = [&](int kc0) {
        #pragma unroll
        for (int p = 0; p < PASSES; ++p) {
            const int idx = p * 256 + tid;
            const int r = idx >> 2;
            const int kq = idx & 3;
            const int row = row0 + r;
            float4 v = make_float4(0.f, 0.f, 0.f, 0.f);
            if (row < n) {
                v = *(const float4*)&X[(size_t)row * IN + kc0 + kq * 4];
                if (RELU_IN) {
                    const float4 b = *(const float4*)&bin[kc0 + kq * 4];
                    v.x = fmaxf(v.x + b.x, 0.f);
                    v.y = fmaxf(v.y + b.y, 0.f);
                    v.z = fmaxf(v.z + b.z, 0.f);
                    v.w = fmaxf(v.w + b.w, 0.f);
                }
            }
            pf[p] = v;
        }
    };

    auto STOREX = [&](float* buf) {
        #pragma unroll
        for (int p = 0; p < PASSES; ++p) {
            const int idx = p * 256 + tid;
            const int r = idx >> 2;
            const int kq = idx & 3;
            buf[(kq * 4 + 0) * ROWS + r] = pf[p].x;
            buf[(kq * 4 + 1) * ROWS + r] = pf[p].y;
            buf[(kq * 4 + 2) * ROWS + r] = pf[p].z;
            buf[(kq * 4 + 3) * ROWS + r] = pf[p].w;
        }
    };

    ull acc[8][4];
    #pragma unroll
    for (int j = 0; j < 8; ++j)
        #pragma unroll
        for (int p = 0; p < 4; ++p) acc[j][p] = 0ull;

    LOADX(0);
    STOREX(xT0);
    __syncthreads();

    for (int c = 0; c < NCHUNK; ++c) {
        float* cur = (c & 1) ? xT1 : xT0;
        float* nxt = (c & 1) ? xT0 : xT1;
        if (c + 1 < NCHUNK) LOADX((c + 1) * KC);

        const int kc0 = c * KC;
        #pragma unroll
        for (int kk = 0; kk < KC; ++kk) {
            const float* xr = &cur[kk * ROWS + ty * 8];
            const float4 xa = *(const float4*)xr;
            const float4 xb = *(const float4*)(xr + 4);
            ull xp[8];
            xp[0] = pack2(xa.x, xa.x); xp[1] = pack2(xa.y, xa.y);
            xp[2] = pack2(xa.z, xa.z); xp[3] = pack2(xa.w, xa.w);
            xp[4] = pack2(xb.x, xb.x); xp[5] = pack2(xb.y, xb.y);
            xp[6] = pack2(xb.z, xb.z); xp[7] = pack2(xb.w, xb.w);

            const ulonglong2* wr = (const ulonglong2*)&Ws[(kc0 + kk) * OUT + tx * 8];
            const ulonglong2 wA = wr[0];
            const ulonglong2 wB = wr[1];
            ull wq[4]; wq[0] = wA.x; wq[1] = wA.y; wq[2] = wB.x; wq[3] = wB.y;

            #pragma unroll
            for (int j = 0; j < 8; ++j) {
                ffma2(acc[j][0], xp[j], wq[0], acc[j][0]);
                ffma2(acc[j][1], xp[j], wq[1], acc[j][1]);
                ffma2(acc[j][2], xp[j], wq[2], acc[j][2]);
                ffma2(acc[j][3], xp[j], wq[3], acc[j][3]);
            }
        }

        if (c + 1 < NCHUNK) STOREX(nxt);
        __syncthreads();
    }

    #pragma unroll
    for (int j = 0; j < 8; ++j) {
        const int row = row0 + ty * 8 + j;
        if (row >= n) continue;
        const float2 a0 = unpack2(acc[j][0]);
        const float2 a1 = unpack2(acc[j][1]);
        const float2 a2 = unpack2(acc[j][2]);
        const float2 a3 = unpack2(acc[j][3]);
        float* hp = &H[(size_t)row * OUT + tx * 8];
        *(float4*)hp = make_float4(a0.x, a0.y, a1.x, a1.y);
        *(float4*)(hp + 4) = make_float4(a2.x, a2.y, a3.x, a3.y);
    }
}

// -------- gather: A[d] = dis[d] * ( dis[d]*H[d] + sum_{s in N(d)} dis[s]*H[s] ) ------
template <int D>
__global__ void gather_kernel(const float* __restrict__ H, float* __restrict__ A, int n) {
    constexpr int LPN = D / 4;
    const long long gt = (long long)blockIdx.x * blockDim.x + threadIdx.x;
    const int node = (int)(gt / LPN);
    const int l = (int)(gt % LPN);
    if (node >= n) return;

    const float4* __restrict__ h4 = (const float4*)H;
    const ull* __restrict__ dis2 = (const ull*)g_dis2;
    const size_t col = (size_t)node * LPN + l;
    const ull dd = __ldg(&dis2[node]);

    float4 sv = h4[col];
    ull acc0, acc1;
    fmul2(acc0, pack2(sv.x, sv.y), dd);
    fmul2(acc1, pack2(sv.z, sv.w), dd);

    const int beg = g_rowstart[node];
    const int cnt = g_deg[node];

    #pragma unroll 4
    for (int j = 0; j < cnt; ++j) {
        const int src = __ldg(&g_csr[beg + j]);
        const ull ss = __ldg(&dis2[src]);
        const float4 v = h4[(size_t)src * LPN + l];
        ffma2(acc0, pack2(v.x, v.y), ss, acc0);
        ffma2(acc1, pack2(v.z, v.w), ss, acc1);
    }

    fmul2(acc0, acc0, dd);
    fmul2(acc1, acc1, dd);
    const float2 a = unpack2(acc0);
    const float2 b = unpack2(acc1);
    ((float4*)A)[col] = make_float4(a.x, a.y, b.x, b.y);
}

// ---------------- final: out = softmax(relu(A2+b2) @ Wf + bf) ----------------
__global__ void final_kernel(const float* __restrict__ A2, const float* __restrict__ b2,
                             const float* __restrict__ Wf, const float* __restrict__ bf,
                             float* __restrict__ out, int n) {
    __shared__ float Wfs[64 * 10];
    __shared__ float bfs[10];
    __shared__ float b2s[64];
    for (int i = threadIdx.x; i < 640; i += blockDim.x) Wfs[i] = Wf[i];
    if (threadIdx.x < 10) bfs[threadIdx.x] = bf[threadIdx.x];
    if (threadIdx.x < 64) b2s[threadIdx.x] = b2[threadIdx.x];
    __syncthreads();

    const int i = blockIdx.x * blockDim.x + threadIdx.x;
    if (i >= n) return;

    float acc[10];
    #pragma unroll
    for (int c = 0; c < 10; ++c) acc[c] = bfs[c];

    #pragma unroll
    for (int kk = 0; kk < 64; kk += 4) {
        float4 v = *(const float4*)&A2[(size_t)i * 64 + kk];
        v.x = fmaxf(v.x + b2s[kk + 0], 0.f);
        v.y = fmaxf(v.y + b2s[kk + 1], 0.f);
        v.z = fmaxf(v.z + b2s[kk + 2], 0.f);
        v.w = fmaxf(v.w + b2s[kk + 3], 0.f);
        #pragma unroll
        for (int c = 0; c < 10; ++c) {
            acc[c] = fmaf(v.x, Wfs[(kk + 0) * 10 + c], acc[c]);
            acc[c] = fmaf(v.y, Wfs[(kk + 1) * 10 + c], acc[c]);
            acc[c] = fmaf(v.z, Wfs[(kk + 2) * 10 + c], acc[c]);
            acc[c] = fmaf(v.w, Wfs[(kk + 3) * 10 + c], acc[c]);
        }
    }

    float m = acc[0];
    #pragma unroll
    for (int c = 1; c < 10; ++c) m = fmaxf(m, acc[c]);
    float s = 0.f;
    float ex[10];
    #pragma unroll
    for (int c = 0; c < 10; ++c) { ex[c] = expf(acc[c] - m); s += ex[c]; }
    const float inv = 1.0f / s;
    #pragma unroll
    for (int c = 0; c < 10; ++c) out[(size_t)i * 10 + c] = ex[c] * inv;
}

// ---------------- launch: CSR build on side stream, overlapped with gemm1 ----------
extern "C" void kernel_launch(void* const* d_in, const int* in_sizes, int n_in,
                              void* d_out, int out_size) {
    const float* x  = (const float*)d_in[0];
    const void*  ei = d_in[1];
    const float* W1 = (const float*)d_in[2];
    const float* b1 = (const float*)d_in[3];
    const float* W2 = (const float*)d_in[4];
    const float* b2 = (const float*)d_in[5];
    const float* Wf = (const float*)d_in[6];
    const float* bf = (const float*)d_in[7];
    float* out = (float*)d_out;

    const long long E = (long long)in_sizes[1] / 2;
    const int n = in_sizes[0] / D1;
    const int nb = (n + SCAN_BLK - 1) / SCAN_BLK;

    float *H1, *A1, *H2, *A2;
    cudaGetSymbolAddress((void**)&H1, g_H1);
    cudaGetSymbolAddress((void**)&A1, g_A1);
    cudaGetSymbolAddress((void**)&H2, g_H2);
    cudaGetSymbolAddress((void**)&A2, g_A2);

    const int smem1 = 128 * 128 * 4 + 2 * 16 * 128 * 4;   // 81920
    const int smem2 = 128 * 64 * 4 + 2 * 16 * 256 * 4;    // 65536
    cudaFuncSetAttribute(gemm_kernel<128, false>,
                         cudaFuncAttributeMaxDynamicSharedMemorySize, smem1);
    cudaFuncSetAttribute(gemm_kernel<64, true>,
                         cudaFuncAttributeMaxDynamicSharedMemorySize, smem2);

    // One-time side-stream + fork/join events (host resources, no device memory).
    static cudaStream_t s1 = nullptr;
    static cudaEvent_t evFork = nullptr, evJoin = nullptr;
    if (!s1) {
        cudaStreamCreateWithFlags(&s1, cudaStreamNonBlocking);
        cudaEventCreateWithFlags(&evFork, cudaEventDisableTiming);
        cudaEventCreateWithFlags(&evJoin, cudaEventDisableTiming);
    }

    // main stream: setup -> fork
    setup_kernel<<<(n + 255) / 256, 256>>>((const unsigned int*)ei, n);
    cudaEventRecord(evFork, 0);
    cudaStreamWaitEvent(s1, evFork, 0);

    // side stream: CSR build chain (depends only on edge_index + g_deg zeroing)
    if (E > 0) count_kernel<<<(int)((E + 255) / 256), 256, 0, s1>>>(ei, E);
    scanA_kernel<<<nb, SCAN_BLK, 0, s1>>>(n);
    // main stream: gemm1 (independent of CSR) — overlaps with the side chain
    gemm_kernel<128, false><<<(n + 127) / 128, 256, smem1>>>(x, W1, nullptr, H1, n);
    scanB_kernel<<<1, MAXNB, 0, s1>>>(nb);
    scanC_kernel<<<nb, SCAN_BLK, 0, s1>>>(n);
    if (E > 0) fill_kernel<<<(int)((E + 255) / 256), 256, 0, s1>>>(ei, E);
    cudaEventRecord(evJoin, s1);

    // join: gather1 needs both gemm1 (main) and CSR (side)
    cudaStreamWaitEvent(0, evJoin, 0);

    gather_kernel<128><<<(int)(((long long)n * 32 + 255) / 256), 256>>>(H1, A1, n);

    gemm_kernel<64, true><<<(n + 255) / 256, 256, smem2>>>(A1, W2, b1, H2, n);
    gather_kernel<64><<<(int)(((long long)n * 16 + 255) / 256), 256>>>(H2, A2, n);

    final_kernel<<<(n + 255) / 256, 256>>>(A2, b2, Wf, bf, out, n);
}

// round 12
// speedup vs baseline: 1.6270x; 1.2080x over previous
#include <cuda_runtime.h>
#include <cuda_bf16.h>
#include <stdint.h>
#include <math.h>

#define NN 100000
#define D1 128
#define D2 64
#define EMAX 4000000
#define SCAN_BLK 1024
#define MAXNB 128

typedef unsigned long long ull;

// ---------------- scratch (static __device__ — no runtime allocation) ----------------
__device__ float  g_dis[NN];
__device__ float2 g_dis2[NN];
__device__ int    g_deg[NN];
__device__ int    g_rowstart[NN];
__device__ int    g_cursor[NN];
__device__ int    g_csr[EMAX];
__device__ int    g_blocksum[MAXNB];
__device__ int    g_blockoff[MAXNB];
__device__ float  g_H1[(size_t)NN * D1];
__device__ float  g_A1[(size_t)NN * D1];
__device__ float  g_H2[(size_t)NN * D2];
__device__ float  g_A2[(size_t)NN * D2];
__device__ int    g_is64;
// W in mma-fragment order: per (col, kstep, tg) one uint4 {hi_b0, hi_b1, lo_b0, lo_b1}
__device__ uint32_t g_Wf1[128 * 8 * 4 * 4];   // 64KB
__device__ uint32_t g_Wf2[64 * 8 * 4 * 4];    // 32KB

// ---------------- f32x2 helpers (gathers) ----------------
__device__ __forceinline__ ull pack2(float lo, float hi) {
    ull r; asm("mov.b64 %0, {%1,%2};" : "=l"(r) : "f"(lo), "f"(hi)); return r;
}
__device__ __forceinline__ float2 unpack2(ull u) {
    float2 f; asm("mov.b64 {%0,%1}, %2;" : "=f"(f.x), "=f"(f.y) : "l"(u)); return f;
}
__device__ __forceinline__ void ffma2(ull& d, ull a, ull b, ull c) {
    asm("fma.rn.f32x2 %0, %1, %2, %3;" : "=l"(d) : "l"(a), "l"(b), "l"(c));
}
__device__ __forceinline__ void fmul2(ull& d, ull a, ull b) {
    asm("mul.rn.f32x2 %0, %1, %2;" : "=l"(d) : "l"(a), "l"(b));
}

__device__ __forceinline__ int load_idx(const void* ei, long long pos, int is64) {
    return is64 ? (int)((const long long*)ei)[pos] : ((const int*)ei)[pos];
}

__device__ __forceinline__ uint32_t pkb(__nv_bfloat16 a, __nv_bfloat16 b) {
    return (uint32_t)__bfloat16_as_ushort(a) | ((uint32_t)__bfloat16_as_ushort(b) << 16);
}

// split float2 -> bf16x2 hi word + bf16x2 lo word (residual)
__device__ __forceinline__ void split2(float2 v, uint32_t& h, uint32_t& l) {
    uint32_t hw;
    asm("cvt.rn.bf16x2.f32 %0, %1, %2;" : "=r"(hw) : "f"(v.y), "f"(v.x));
    const float hx = __uint_as_float(hw << 16);
    const float hy = __uint_as_float(hw & 0xffff0000u);
    const float lx = v.x - hx;
    const float ly = v.y - hy;
    uint32_t lw;
    asm("cvt.rn.bf16x2.f32 %0, %1, %2;" : "=r"(lw) : "f"(ly), "f"(lx));
    h = hw; l = lw;
}

__device__ __forceinline__ void mma16816(float* c, const uint32_t* a, uint32_t b0, uint32_t b1) {
    asm volatile(
        "mma.sync.aligned.m16n8k16.row.col.f32.bf16.bf16.f32 "
        "{%0,%1,%2,%3}, {%4,%5,%6,%7}, {%8,%9}, {%0,%1,%2,%3};"
        : "+f"(c[0]), "+f"(c[1]), "+f"(c[2]), "+f"(c[3])
        : "r"(a[0]), "r"(a[1]), "r"(a[2]), "r"(a[3]), "r"(b0), "r"(b1));
}

// ---------------- setup / CSR build ----------------
__global__ void setup_kernel(const unsigned int* ei, int n) {
    int i = blockIdx.x * blockDim.x + threadIdx.x;
    if (i < n) g_deg[i] = 0;
    if (blockIdx.x == 0) {
        __shared__ int any;
        if (threadIdx.x == 0) any = 0;
        __syncthreads();
        int local = 0;
        for (int j = threadIdx.x; j < 2048; j += blockDim.x)
            if (ei[2 * j + 1] != 0u) local = 1;
        if (local) any = 1;
        __syncthreads();
        if (threadIdx.x == 0) g_is64 = (any == 0) ? 1 : 0;
    }
}

__global__ void count_kernel(const void* __restrict__ ei, long long E) {
    long long e = (long long)blockIdx.x * blockDim.x + threadIdx.x;
    if (e >= E) return;
    int dst = load_idx(ei, E + e, g_is64);
    atomicAdd(&g_deg[dst], 1);
}

__global__ void scanA_kernel(int n) {
    __shared__ int s[SCAN_BLK];
    int i = blockIdx.x * SCAN_BLK + threadIdx.x;
    s[threadIdx.x] = (i < n) ? g_deg[i] : 0;
    __syncthreads();
    for (int off = SCAN_BLK / 2; off > 0; off >>= 1) {
        if (threadIdx.x < off) s[threadIdx.x] += s[threadIdx.x + off];
        __syncthreads();
    }
    if (threadIdx.x == 0) g_blocksum[blockIdx.x] = s[0];
}

__global__ void scanB_kernel(int nb) {
    __shared__ int s[MAXNB];
    int v = (threadIdx.x < nb) ? g_blocksum[threadIdx.x] : 0;
    s[threadIdx.x] = v;
    __syncthreads();
    for (int off = 1; off < MAXNB; off <<= 1) {
        int t = (threadIdx.x >= off) ? s[threadIdx.x - off] : 0;
        __syncthreads();
        s[threadIdx.x] += t;
        __syncthreads();
    }
    if (threadIdx.x < nb) g_blockoff[threadIdx.x] = s[threadIdx.x] - v;
}

__global__ void scanC_kernel(int n) {
    __shared__ int s[SCAN_BLK];
    int i = blockIdx.x * SCAN_BLK + threadIdx.x;
    int v = (i < n) ? g_deg[i] : 0;
    s[threadIdx.x] = v;
    __syncthreads();
    for (int off = 1; off < SCAN_BLK; off <<= 1) {
        int t = (threadIdx.x >= off) ? s[threadIdx.x - off] : 0;
        __syncthreads();
        s[threadIdx.x] += t;
        __syncthreads();
    }
    if (i < n) {
        int excl = s[threadIdx.x] - v + g_blockoff[blockIdx.x];
        g_rowstart[i] = excl;
        g_cursor[i] = excl;
        float d = rsqrtf((float)(v + 1));
        g_dis[i] = d;
        g_dis2[i] = make_float2(d, d);
    }
}

__global__ void fill_kernel(const void* __restrict__ ei, long long E) {
    long long e = (long long)blockIdx.x * blockDim.x + threadIdx.x;
    if (e >= E) return;
    const int is64 = g_is64;
    int src = load_idx(ei, e, is64);
    int dst = load_idx(ei, E + e, is64);
    int pos = atomicAdd(&g_cursor[dst], 1);
    g_csr[pos] = src;
}

// ---------------- weight prep: fragment-order bf16 hi/lo pack ----------------
// W [K=128][OUT] row-major -> per (c, w=k/2): hi word (k,k+1), lo word.
// Frag uint4 index = (c*8 + ks)*4 + tg; words: [hi_slot0, hi_slot1, lo_slot0, lo_slot1].
__global__ void prep_w_kernel(const float* __restrict__ W1, const float* __restrict__ W2) {
    const int idx = blockIdx.x * blockDim.x + threadIdx.x;
    if (idx < 128 * 64) {
        const int c = idx >> 6, w = idx & 63;
        const int k = w * 2;
        const float x0 = W1[k * 128 + c], x1 = W1[(k + 1) * 128 + c];
        const __nv_bfloat16 h0 = __float2bfloat16_rn(x0), h1 = __float2bfloat16_rn(x1);
        const uint32_t hw = pkb(h0, h1);
        const uint32_t lw = pkb(__float2bfloat16_rn(x0 - __bfloat162float(h0)),
                                __float2bfloat16_rn(x1 - __bfloat162float(h1)));
        const int ks = w >> 3, wi = w & 7, tg = wi & 3, slot = wi >> 2;
        const int frag = (c * 8 + ks) * 4 + tg;
        g_Wf1[frag * 4 + slot] = hw;
        g_Wf1[frag * 4 + 2 + slot] = lw;
    }
    if (idx < 64 * 64) {
        const int c = idx >> 6, w = idx & 63;
        const int k = w * 2;
        const float x0 = W2[k * 64 + c], x1 = W2[(k + 1) * 64 + c];
        const __nv_bfloat16 h0 = __float2bfloat16_rn(x0), h1 = __float2bfloat16_rn(x1);
        const uint32_t hw = pkb(h0, h1);
        const uint32_t lw = pkb(__float2bfloat16_rn(x0 - __bfloat162float(h0)),
                                __float2bfloat16_rn(x1 - __bfloat162float(h1)));
        const int ks = w >> 3, wi = w & 7, tg = wi & 3, slot = wi >> 2;
        const int frag = (c * 8 + ks) * 4 + tg;
        g_Wf2[frag * 4 + slot] = hw;
        g_Wf2[frag * 4 + 2 + slot] = lw;
    }
}

// ---------------- HMMA GEMM: H = X@W, bf16 hi/lo split, fp32 accum -----------------
// IN=128. Block: 256 thr = 8 warps; warp tile 32 rows x 32 cols; block tile 128x64.
// Grid: (ceil(n/128), OUT/64). X row length fixed 128. Optional relu(X+bin) on load.
template <int OUT, bool RELU_IN>
__global__ void __launch_bounds__(256)
mma_gemm_kernel(const float* __restrict__ X, const uint32_t* __restrict__ Wf,
                const float* __restrict__ bin, float* __restrict__ H, int n) {
    __shared__ uint4 bs[2048];                 // 64 cols x 8 ks x 4 tg = 32KB

    const int tid = threadIdx.x;
    const int lane = tid & 31;
    const int wid = tid >> 5;
    const int wr = wid >> 1;                   // warp row group (0..3)
    const int wc = wid & 1;                    // warp col group (0..1)
    const int g = lane >> 2;                   // groupID
    const int tg = lane & 3;                   // thread in group
    const int row0 = blockIdx.x * 128;
    const int cb = blockIdx.y * 64;

    // stage W slab (cols cb..cb+63): contiguous 2048 uint4
    {
        const uint4* src = (const uint4*)Wf + cb * 32;
        #pragma unroll
        for (int i = tid; i < 2048; i += 256) bs[i] = src[i];
    }
    __syncthreads();

    float acc[2][4][4];
    #pragma unroll
    for (int mt = 0; mt < 2; ++mt)
        #pragma unroll
        for (int nt = 0; nt < 4; ++nt)
            #pragma unroll
            for (int q = 0; q < 4; ++q) acc[mt][nt][q] = 0.f;

    const int rbase = row0 + wr * 32;

    auto ld2 = [&](int r, int k) -> float2 {
        if (r >= n) return make_float2(0.f, 0.f);
        float2 v = *(const float2*)&X[(size_t)r * 128 + k];
        if (RELU_IN) {
            const float2 b = *(const float2*)&bin[k];
            v.x = fmaxf(v.x + b.x, 0.f);
            v.y = fmaxf(v.y + b.y, 0.f);
        }
        return v;
    };

    #pragma unroll
    for (int ks = 0; ks < 8; ++ks) {
        // ---- A fragments (hi/lo) straight from global fp32 ----
        uint32_t ah[2][4], al[2][4];
        const int k0 = ks * 16 + tg * 2;
        #pragma unroll
        for (int mt = 0; mt < 2; ++mt) {
            const int r0 = rbase + mt * 16 + g;
            const int r1 = r0 + 8;
            split2(ld2(r0, k0),     ah[mt][0], al[mt][0]);
            split2(ld2(r1, k0),     ah[mt][1], al[mt][1]);
            split2(ld2(r0, k0 + 8), ah[mt][2], al[mt][2]);
            split2(ld2(r1, k0 + 8), ah[mt][3], al[mt][3]);
        }
        // ---- B fragments from smem (one LDS.128 per n-tile) ----
        uint32_t bh0[4], bh1[4], bl0[4], bl1[4];
        #pragma unroll
        for (int nt = 0; nt < 4; ++nt) {
            const int cl = wc * 32 + nt * 8 + g;
            const uint4 b = bs[(cl * 8 + ks) * 4 + tg];
            bh0[nt] = b.x; bh1[nt] = b.y; bl0[nt] = b.z; bl1[nt] = b.w;
        }
        // ---- 3-pass split MMA ----
        #pragma unroll
        for (int mt = 0; mt < 2; ++mt)
            #pragma unroll
            for (int nt = 0; nt < 4; ++nt) {
                mma16816(acc[mt][nt], ah[mt], bh0[nt], bh1[nt]);
                mma16816(acc[mt][nt], ah[mt], bl0[nt], bl1[nt]);
                mma16816(acc[mt][nt], al[mt], bh0[nt], bh1[nt]);
            }
    }

    // ---- epilogue ----
    #pragma unroll
    for (int mt = 0; mt < 2; ++mt) {
        const int r0 = rbase + mt * 16 + g;
        const int r1 = r0 + 8;
        #pragma unroll
        for (int nt = 0; nt < 4; ++nt) {
            const int c0 = cb + wc * 32 + nt * 8 + tg * 2;
            if (r0 < n)
                *(float2*)&H[(size_t)r0 * OUT + c0] = make_float2(acc[mt][nt][0], acc[mt][nt][1]);
            if (r1 < n)
                *(float2*)&H[(size_t)r1 * OUT + c0] = make_float2(acc[mt][nt][2], acc[mt][nt][3]);
        }
    }
}

// -------- gather: A[d] = dis[d] * ( dis[d]*H[d] + sum_{s in N(d)} dis[s]*H[s] ) ------
template <int D>
__global__ void gather_kernel(const float* __restrict__ H, float* __restrict__ A, int n) {
    constexpr int LPN = D / 4;
    const long long gt = (long long)blockIdx.x * blockDim.x + threadIdx.x;
    const int node = (int)(gt / LPN);
    const int l = (int)(gt % LPN);
    if (node >= n) return;

    const float4* __restrict__ h4 = (const float4*)H;
    const ull* __restrict__ dis2 = (const ull*)g_dis2;
    const size_t col = (size_t)node * LPN + l;
    const ull dd = __ldg(&dis2[node]);

    float4 sv = h4[col];
    ull acc0, acc1;
    fmul2(acc0, pack2(sv.x, sv.y), dd);
    fmul2(acc1, pack2(sv.z, sv.w), dd);

    const int beg = g_rowstart[node];
    const int cnt = g_deg[node];

    #pragma unroll 4
    for (int j = 0; j < cnt; ++j) {
        const int src = __ldg(&g_csr[beg + j]);
        const ull ss = __ldg(&dis2[src]);
        const float4 v = h4[(size_t)src * LPN + l];
        ffma2(acc0, pack2(v.x, v.y), ss, acc0);
        ffma2(acc1, pack2(v.z, v.w), ss, acc1);
    }

    fmul2(acc0, acc0, dd);
    fmul2(acc1, acc1, dd);
    const float2 a = unpack2(acc0);
    const float2 b = unpack2(acc1);
    ((float4*)A)[col] = make_float4(a.x, a.y, b.x, b.y);
}

// ---------------- final: out = softmax(relu(A2+b2) @ Wf + bf) ----------------
__global__ void final_kernel(const float* __restrict__ A2, const float* __restrict__ b2,
                             const float* __restrict__ Wf, const float* __restrict__ bf,
                             float* __restrict__ out, int n) {
    __shared__ float Wfs[64 * 10];
    __shared__ float bfs[10];
    __shared__ float b2s[64];
    for (int i = threadIdx.x; i < 640; i += blockDim.x) Wfs[i] = Wf[i];
    if (threadIdx.x < 10) bfs[threadIdx.x] = bf[threadIdx.x];
    if (threadIdx.x < 64) b2s[threadIdx.x] = b2[threadIdx.x];
    __syncthreads();

    const int i = blockIdx.x * blockDim.x + threadIdx.x;
    if (i >= n) return;

    float acc[10];
    #pragma unroll
    for (int c = 0; c < 10; ++c) acc[c] = bfs[c];

    #pragma unroll
    for (int kk = 0; kk < 64; kk += 4) {
        float4 v = *(const float4*)&A2[(size_t)i * 64 + kk];
        v.x = fmaxf(v.x + b2s[kk + 0], 0.f);
        v.y = fmaxf(v.y + b2s[kk + 1], 0.f);
        v.z = fmaxf(v.z + b2s[kk + 2], 0.f);
        v.w = fmaxf(v.w + b2s[kk + 3], 0.f);
        #pragma unroll
        for (int c = 0; c < 10; ++c) {
            acc[c] = fmaf(v.x, Wfs[(kk + 0) * 10 + c], acc[c]);
            acc[c] = fmaf(v.y, Wfs[(kk + 1) * 10 + c], acc[c]);
            acc[c] = fmaf(v.z, Wfs[(kk + 2) * 10 + c], acc[c]);
            acc[c] = fmaf(v.w, Wfs[(kk + 3) * 10 + c], acc[c]);
        }
    }

    float m = acc[0];
    #pragma unroll
    for (int c = 1; c < 10; ++c) m = fmaxf(m, acc[c]);
    float s = 0.f;
    float ex[10];
    #pragma unroll
    for (int c = 0; c < 10; ++c) { ex[c] = expf(acc[c] - m); s += ex[c]; }
    const float inv = 1.0f / s;
    #pragma unroll
    for (int c = 0; c < 10; ++c) out[(size_t)i * 10 + c] = ex[c] * inv;
}

// ---------------- launch ----------------
extern "C" void kernel_launch(void* const* d_in, const int* in_sizes, int n_in,
                              void* d_out, int out_size) {
    const float* x  = (const float*)d_in[0];
    const void*  ei = d_in[1];
    const float* W1 = (const float*)d_in[2];
    const float* b1 = (const float*)d_in[3];
    const float* W2 = (const float*)d_in[4];
    const float* b2 = (const float*)d_in[5];
    const float* Wf = (const float*)d_in[6];
    const float* bf = (const float*)d_in[7];
    float* out = (float*)d_out;

    const long long E = (long long)in_sizes[1] / 2;
    const int n = in_sizes[0] / D1;
    const int nb = (n + SCAN_BLK - 1) / SCAN_BLK;

    float *H1, *A1, *H2, *A2;
    cudaGetSymbolAddress((void**)&H1, g_H1);
    cudaGetSymbolAddress((void**)&A1, g_A1);
    cudaGetSymbolAddress((void**)&H2, g_H2);
    cudaGetSymbolAddress((void**)&A2, g_A2);
    uint32_t *Wf1, *Wf2;
    cudaGetSymbolAddress((void**)&Wf1, g_Wf1);
    cudaGetSymbolAddress((void**)&Wf2, g_Wf2);

    static cudaStream_t s1 = nullptr;
    static cudaEvent_t evFork = nullptr, evJoin = nullptr;
    if (!s1) {
        cudaStreamCreateWithFlags(&s1, cudaStreamNonBlocking);
        cudaEventCreateWithFlags(&evFork, cudaEventDisableTiming);
        cudaEventCreateWithFlags(&evJoin, cudaEventDisableTiming);
    }

    const int rowb = (n + 127) / 128;

    // fork: CSR build chain on side stream (depends only on edge_index)
    cudaEventRecord(evFork, 0);
    cudaStreamWaitEvent(s1, evFork, 0);
    setup_kernel<<<(n + 255) / 256, 256, 0, s1>>>((const unsigned int*)ei, n);
    if (E > 0) count_kernel<<<(int)((E + 255) / 256), 256, 0, s1>>>(ei, E);
    scanA_kernel<<<nb, SCAN_BLK, 0, s1>>>(n);
    scanB_kernel<<<1, MAXNB, 0, s1>>>(nb);
    scanC_kernel<<<nb, SCAN_BLK, 0, s1>>>(n);
    if (E > 0) fill_kernel<<<(int)((E + 255) / 256), 256, 0, s1>>>(ei, E);
    cudaEventRecord(evJoin, s1);

    // main stream: weight prep + HMMA gemm1 (overlaps with CSR build)
    prep_w_kernel<<<32, 256>>>(W1, W2);
    mma_gemm_kernel<128, false><<<dim3(rowb, 2), 256>>>(x, Wf1, nullptr, H1, n);

    // join: gather1 needs gemm1 (main) + CSR (side)
    cudaStreamWaitEvent(0, evJoin, 0);

    gather_kernel<128><<<(int)(((long long)n * 32 + 255) / 256), 256>>>(H1, A1, n);

    mma_gemm_kernel<64, true><<<dim3(rowb, 1), 256>>>(A1, Wf2, b1, H2, n);
    gather_kernel<64><<<(int)(((long long)n * 16 + 255) / 256), 256>>>(H2, A2, n);

    final_kernel<<<(n + 255) / 256, 256>>>(A2, b2, Wf, bf, out, n);
}